// round 2
// baseline (speedup 1.0000x reference)
#include <cuda_runtime.h>

#define N_NODES 50000
#define N_EDGES 800000
#define IN_F    128
#define OUT_F   128
#define EDGE_F  16
#define HEADS   4

// Scratch (static device arrays; no allocation APIs allowed)
__device__ float g_Q[N_NODES * OUT_F];
__device__ float g_K[N_NODES * OUT_F];
__device__ float g_V[N_NODES * OUT_F];
__device__ float g_denom[N_NODES * HEADS];

// ---------------------------------------------------------------------------
// Zero the denom accumulator (must be re-zeroed every launch: graph-replayable)
// ---------------------------------------------------------------------------
__global__ void zero_denom_kernel() {
    int i = blockIdx.x * blockDim.x + threadIdx.x;
    if (i < N_NODES * HEADS) g_denom[i] = 0.0f;
}

// ---------------------------------------------------------------------------
// Fused QKV GEMM: [50000,128] x 3x[128,128] (fp32)
// Block: 384 threads, thread t -> matrix m=t/128, output col c=t%128.
// Each block handles 16 rows; x tile transposed in smem so the inner loop
// reads 4x LDS.128 broadcasts per k instead of 16 scalar LDS.
// ---------------------------------------------------------------------------
#define ROWS_PB   16
#define XS_STRIDE 20   // 16 rows + pad; keeps float4 alignment, spreads banks

__global__ __launch_bounds__(384) void qkv_gemm_kernel(
    const float* __restrict__ x,
    const float* __restrict__ Wq,
    const float* __restrict__ Wk,
    const float* __restrict__ Wv)
{
    __shared__ float xs[128 * XS_STRIDE];

    int row0 = blockIdx.x * ROWS_PB;
    int t = threadIdx.x;

    // Load 16 rows of x, transposed: xs[k][r]
    for (int idx = t; idx < ROWS_PB * 128; idx += 384) {
        int r = idx >> 7;
        int k = idx & 127;
        xs[k * XS_STRIDE + r] = x[(size_t)(row0 + r) * 128 + k];
    }
    __syncthreads();

    int m = t >> 7;        // 0=Q, 1=K, 2=V
    int c = t & 127;       // output column
    const float* W = (m == 0) ? Wq : ((m == 1) ? Wk : Wv);

    float acc[ROWS_PB];
#pragma unroll
    for (int r = 0; r < ROWS_PB; r++) acc[r] = 0.0f;

#pragma unroll 8
    for (int k = 0; k < 128; k++) {
        float w = __ldg(W + (size_t)k * 128 + c);
        const float4* xr = (const float4*)(xs + k * XS_STRIDE);
        float4 a0 = xr[0];
        float4 a1 = xr[1];
        float4 a2 = xr[2];
        float4 a3 = xr[3];
        acc[0]  = fmaf(a0.x, w, acc[0]);
        acc[1]  = fmaf(a0.y, w, acc[1]);
        acc[2]  = fmaf(a0.z, w, acc[2]);
        acc[3]  = fmaf(a0.w, w, acc[3]);
        acc[4]  = fmaf(a1.x, w, acc[4]);
        acc[5]  = fmaf(a1.y, w, acc[5]);
        acc[6]  = fmaf(a1.z, w, acc[6]);
        acc[7]  = fmaf(a1.w, w, acc[7]);
        acc[8]  = fmaf(a2.x, w, acc[8]);
        acc[9]  = fmaf(a2.y, w, acc[9]);
        acc[10] = fmaf(a2.z, w, acc[10]);
        acc[11] = fmaf(a2.w, w, acc[11]);
        acc[12] = fmaf(a3.x, w, acc[12]);
        acc[13] = fmaf(a3.y, w, acc[13]);
        acc[14] = fmaf(a3.z, w, acc[14]);
        acc[15] = fmaf(a3.w, w, acc[15]);
    }

    float* out = (m == 0) ? g_Q : ((m == 1) ? g_K : g_V);
#pragma unroll
    for (int r = 0; r < ROWS_PB; r++) {
        out[(size_t)(row0 + r) * 128 + c] = acc[r];
    }
}

// ---------------------------------------------------------------------------
// Edge kernel: one warp per edge.
// Lane i loads float4 chunks of Q[src] and K[dst]; 8-lane groups reduce per
// head; lanes {0,8,16,24} add the edge bias, exp, and atomicAdd into denom.
// edge_index arrives as int32 (harness narrows the reference's int64).
// ---------------------------------------------------------------------------
__global__ __launch_bounds__(256) void edge_kernel(
    const int* __restrict__ edge_index,
    const float* __restrict__ edge_attr,
    const float* __restrict__ We)
{
    __shared__ float sWe[EDGE_F * HEADS];
    if (threadIdx.x < EDGE_F * HEADS) sWe[threadIdx.x] = We[threadIdx.x];
    __syncthreads();

    int e = (int)((blockIdx.x * 256 + threadIdx.x) >> 5);
    int lane = threadIdx.x & 31;
    if (e >= N_EDGES) return;

    int src = edge_index[e];             // broadcast load (same addr / warp)
    int dst = edge_index[N_EDGES + e];

    // Safety guard: converts any index-decoding surprise into a rel_err
    // diagnostic instead of an illegal access. Near-free (uniform branch).
    if ((unsigned)src >= N_NODES || (unsigned)dst >= N_NODES) return;

    float4 q = *(const float4*)(g_Q + (size_t)src * 128 + lane * 4);
    float4 k = *(const float4*)(g_K + (size_t)dst * 128 + lane * 4);
    float p = q.x * k.x + q.y * k.y + q.z * k.z + q.w * k.w;

    // reduce within each 8-lane (one head = 32 dims) group
    p += __shfl_xor_sync(0xffffffffu, p, 1);
    p += __shfl_xor_sync(0xffffffffu, p, 2);
    p += __shfl_xor_sync(0xffffffffu, p, 4);

    if ((lane & 7) == 0) {
        int h = lane >> 3;
        const float* ea = edge_attr + (size_t)e * EDGE_F;
        float bias = 0.0f;
#pragma unroll
        for (int f = 0; f < EDGE_F; f++) bias = fmaf(ea[f], sWe[f * HEADS + h], bias);
        float score = p * 0.17677669529663687f + bias;   // 1/sqrt(32)
        atomicAdd(&g_denom[(size_t)dst * HEADS + h], expf(score));
    }
}

// ---------------------------------------------------------------------------
// Final kernel: one warp per node.
// out[n] = LayerNorm( x[n] + V[n] * denom/(denom+1e-10) ) * gamma + beta
// Two-pass mean/var to match the reference math exactly.
// ---------------------------------------------------------------------------
__global__ __launch_bounds__(256) void final_kernel(
    const float* __restrict__ x,
    const float* __restrict__ gamma,
    const float* __restrict__ beta,
    float* __restrict__ out)
{
    int n = (int)((blockIdx.x * 256 + threadIdx.x) >> 5);
    int lane = threadIdx.x & 31;
    if (n >= N_NODES) return;

    int h = lane >> 3;                    // head for this lane's 4 dims
    float d = g_denom[(size_t)n * HEADS + h];
    float fac = d / (d + 1e-10f);

    float4 xv = *(const float4*)(x + (size_t)n * 128 + lane * 4);
    float4 vv = *(const float4*)(g_V + (size_t)n * 128 + lane * 4);

    float4 hv;
    hv.x = fmaf(vv.x, fac, xv.x);
    hv.y = fmaf(vv.y, fac, xv.y);
    hv.z = fmaf(vv.z, fac, xv.z);
    hv.w = fmaf(vv.w, fac, xv.w);

    // mean
    float s = hv.x + hv.y + hv.z + hv.w;
#pragma unroll
    for (int o = 16; o > 0; o >>= 1) s += __shfl_xor_sync(0xffffffffu, s, o);
    float mu = s * (1.0f / 128.0f);

    // variance (two-pass, like reference)
    float dx0 = hv.x - mu, dx1 = hv.y - mu, dx2 = hv.z - mu, dx3 = hv.w - mu;
    float sq = dx0 * dx0 + dx1 * dx1 + dx2 * dx2 + dx3 * dx3;
#pragma unroll
    for (int o = 16; o > 0; o >>= 1) sq += __shfl_xor_sync(0xffffffffu, sq, o);
    float var = sq * (1.0f / 128.0f);
    float inv = rsqrtf(var + 1e-5f);

    float4 g = *(const float4*)(gamma + lane * 4);
    float4 b = *(const float4*)(beta + lane * 4);

    float4 o4;
    o4.x = fmaf(dx0 * inv, g.x, b.x);
    o4.y = fmaf(dx1 * inv, g.y, b.y);
    o4.z = fmaf(dx2 * inv, g.z, b.z);
    o4.w = fmaf(dx3 * inv, g.w, b.w);

    *(float4*)(out + (size_t)n * 128 + lane * 4) = o4;
}

// ---------------------------------------------------------------------------
extern "C" void kernel_launch(void* const* d_in, const int* in_sizes, int n_in,
                              void* d_out, int out_size)
{
    const float* x          = (const float*)d_in[0];
    const int*   edge_index = (const int*)d_in[1];
    const float* edge_attr  = (const float*)d_in[2];
    const float* Wq         = (const float*)d_in[3];
    const float* Wk         = (const float*)d_in[4];
    const float* Wv         = (const float*)d_in[5];
    const float* We         = (const float*)d_in[6];
    const float* gamma      = (const float*)d_in[7];
    const float* beta       = (const float*)d_in[8];
    float*       out        = (float*)d_out;

    zero_denom_kernel<<<(N_NODES * HEADS + 255) / 256, 256>>>();
    qkv_gemm_kernel<<<N_NODES / ROWS_PB, 384>>>(x, Wq, Wk, Wv);
    edge_kernel<<<(N_EDGES * 32) / 256, 256>>>(edge_index, edge_attr, We);
    final_kernel<<<(N_NODES * 32 + 255) / 256, 256>>>(x, gamma, beta, out);
}

// round 3
// speedup vs baseline: 3.8321x; 3.8321x over previous
#include <cuda_runtime.h>

#define N_NODES 50000
#define N_EDGES 800000

// In-degree >= 1 flag per node. fac = denom/(denom+1e-10) equals this flag to
// ~3e-9 absolute (denom >= exp(min score) ~ 0.03 whenever degree >= 1; exactly
// 0 when degree == 0), so the whole Q/K/edge-softmax pipeline collapses to it.
__device__ int g_flag[N_NODES];

// ---------------------------------------------------------------------------
__global__ void zero_flags_kernel() {
    int i = blockIdx.x * blockDim.x + threadIdx.x;
    if (i < N_NODES) g_flag[i] = 0;
}

__global__ void mark_flags_kernel(const int* __restrict__ edge_index) {
    int e = blockIdx.x * blockDim.x + threadIdx.x;
    if (e < N_EDGES) {
        int dst = edge_index[N_EDGES + e];   // dst row of edge_index (int32)
        if ((unsigned)dst < N_NODES) g_flag[dst] = 1;
    }
}

// ---------------------------------------------------------------------------
// Fused: V = x @ Wv  ->  h = x + V*flag  ->  LayerNorm(h)*gamma + beta
// Block = 128 threads (thread c = output column), 32 rows per block.
// x tile is stored transposed in smem so the GEMM inner loop does
// 8x LDS.128 + 1 coalesced Wv load + 32 FMA per k.
// ---------------------------------------------------------------------------
#define ROWS_PB   32
#define XS_STRIDE 36   // 32 rows + pad (keeps float4 alignment, spreads banks)

__global__ __launch_bounds__(128) void fused_v_ln_kernel(
    const float* __restrict__ x,
    const float* __restrict__ Wv,
    const float* __restrict__ gamma,
    const float* __restrict__ beta,
    float* __restrict__ out)
{
    __shared__ float xs[128 * XS_STRIDE];     // xs[k][r] (transposed tile)
    __shared__ float hs[ROWS_PB][132];        // h rows for LN reduction
    __shared__ float s_mu[ROWS_PB], s_inv[ROWS_PB];

    int row0 = blockIdx.x * ROWS_PB;
    int c = threadIdx.x;                      // 0..127, output column

    // Load 32 rows of x, transposed (tail block clamps row index; results for
    // clamped rows are discarded at the guarded store).
    for (int idx = c; idx < ROWS_PB * 128; idx += 128) {
        int r = idx >> 7;
        int k = idx & 127;
        int rr = min(row0 + r, N_NODES - 1);
        xs[k * XS_STRIDE + r] = x[(size_t)rr * 128 + k];
    }
    __syncthreads();

    float acc[ROWS_PB];
#pragma unroll
    for (int r = 0; r < ROWS_PB; r++) acc[r] = 0.0f;

#pragma unroll 4
    for (int k = 0; k < 128; k++) {
        float w = __ldg(Wv + (size_t)k * 128 + c);
        const float4* xr = (const float4*)(xs + k * XS_STRIDE);
#pragma unroll
        for (int i = 0; i < 8; i++) {
            float4 a = xr[i];
            acc[i * 4 + 0] = fmaf(a.x, w, acc[i * 4 + 0]);
            acc[i * 4 + 1] = fmaf(a.y, w, acc[i * 4 + 1]);
            acc[i * 4 + 2] = fmaf(a.z, w, acc[i * 4 + 2]);
            acc[i * 4 + 3] = fmaf(a.w, w, acc[i * 4 + 3]);
        }
    }

    // h = x + V*flag  (x re-read coalesced from gmem: L2 hit; avoids
    // 4-way-bank-conflicted transposed LDS for the residual)
#pragma unroll
    for (int r = 0; r < ROWS_PB; r++) {
        int rr = min(row0 + r, N_NODES - 1);
        float fac = (float)g_flag[rr];                 // warp-broadcast load
        float xv = x[(size_t)rr * 128 + c];
        hs[r][c] = fmaf(acc[r], fac, xv);
    }
    __syncthreads();

    // Per-row mean/var: warp w reduces rows [w*8, w*8+8)
    int wrp = c >> 5, lane = c & 31;
    for (int r = wrp * 8; r < wrp * 8 + 8; r++) {
        float s = hs[r][lane] + hs[r][lane + 32] + hs[r][lane + 64] + hs[r][lane + 96];
#pragma unroll
        for (int o = 16; o > 0; o >>= 1) s += __shfl_xor_sync(0xffffffffu, s, o);
        float mu = s * (1.0f / 128.0f);

        float d0 = hs[r][lane]      - mu;
        float d1 = hs[r][lane + 32] - mu;
        float d2 = hs[r][lane + 64] - mu;
        float d3 = hs[r][lane + 96] - mu;
        float sq = d0 * d0 + d1 * d1 + d2 * d2 + d3 * d3;
#pragma unroll
        for (int o = 16; o > 0; o >>= 1) sq += __shfl_xor_sync(0xffffffffu, sq, o);

        if (lane == 0) {
            s_mu[r]  = mu;
            s_inv[r] = rsqrtf(sq * (1.0f / 128.0f) + 1e-5f);
        }
    }
    __syncthreads();

    float gm = gamma[c], bt = beta[c];
#pragma unroll 4
    for (int r = 0; r < ROWS_PB; r++) {
        int rw = row0 + r;
        if (rw < N_NODES) {
            out[(size_t)rw * 128 + c] =
                fmaf((hs[r][c] - s_mu[r]) * s_inv[r], gm, bt);
        }
    }
}

// ---------------------------------------------------------------------------
extern "C" void kernel_launch(void* const* d_in, const int* in_sizes, int n_in,
                              void* d_out, int out_size)
{
    const float* x          = (const float*)d_in[0];
    const int*   edge_index = (const int*)d_in[1];
    const float* Wv         = (const float*)d_in[5];
    const float* gamma      = (const float*)d_in[7];
    const float* beta       = (const float*)d_in[8];
    float*       out        = (float*)d_out;

    zero_flags_kernel<<<(N_NODES + 255) / 256, 256>>>();
    mark_flags_kernel<<<(N_EDGES + 255) / 256, 256>>>(edge_index);
    fused_v_ln_kernel<<<(N_NODES + ROWS_PB - 1) / ROWS_PB, 128>>>(x, Wv, gamma, beta, out);
}

// round 5
// speedup vs baseline: 8.1148x; 2.1176x over previous
#include <cuda_runtime.h>
#include <cuda_bf16.h>
#include <cstdint>

#define N_NODES 50000
#define N_EDGES 800000

#define M_TILE   128
#define THREADS  256
#define N_BLOCKS ((N_NODES + M_TILE - 1) / M_TILE)   // 391

// ---------------------------------------------------------------------------
// Device scratch (no allocation APIs allowed)
// ---------------------------------------------------------------------------
__device__ int g_flag[N_NODES];                              // in-degree>=1
__device__ __align__(16) unsigned char g_WimgHi[32768];      // swizzled bf16 img of Wv^T
__device__ __align__(16) unsigned char g_WimgLo[32768];

// ---------------------------------------------------------------------------
// Blocked SW128 atom layout for a [128 rows x 128 k] bf16 tile.
// atom = 8 rows x 64 bf16 (1024B); 16 atom-rows, 2 atom-cols.
// tile_off(r,k) = ((r>>3)+((k>>6)<<4))*1024 + (r&7)*128 + ((k&63)*2 ^ ((r&7)<<4))
// The XOR keeps every (8-row x 16B-chunk) access pattern bank-conflict-free.
// ---------------------------------------------------------------------------
__host__ __device__ __forceinline__ uint32_t tile_off(int r, int k) {
    uint32_t off = ((uint32_t)((r >> 3) + ((k >> 6) << 4))) * 1024u
                 + (uint32_t)(r & 7) * 128u + (uint32_t)(k & 63) * 2u;
    return off ^ ((off >> 3) & 0x70);
}

// ---------------------------------------------------------------------------
// Warp-level bf16 MMA (sm_80+, runs as HMMA on sm_100)
// D(16x8,f32) += A(16x16,bf16,row) * B(16x8,bf16,col)
// ---------------------------------------------------------------------------
__device__ __forceinline__ void mma16816(float* d, const uint32_t* a, const uint32_t* b) {
    asm volatile(
        "mma.sync.aligned.m16n8k16.row.col.f32.bf16.bf16.f32 "
        "{%0,%1,%2,%3}, {%4,%5,%6,%7}, {%8,%9}, {%0,%1,%2,%3};"
        : "+f"(d[0]), "+f"(d[1]), "+f"(d[2]), "+f"(d[3])
        : "r"(a[0]), "r"(a[1]), "r"(a[2]), "r"(a[3]), "r"(b[0]), "r"(b[1]));
}

// ---------------------------------------------------------------------------
// Kernel 1: zero flags + build swizzled bf16 hi/lo images of Wv^T
// (B operand: Wt[n][k] = Wv[k][n])
// ---------------------------------------------------------------------------
#define ZERO_BLOCKS ((N_NODES + 255) / 256)
__global__ void prep_kernel(const float* __restrict__ Wv) {
    int b = blockIdx.x;
    if (b < ZERO_BLOCKS) {
        int i = b * 256 + threadIdx.x;
        if (i < N_NODES) g_flag[i] = 0;
    } else {
        int idx = (b - ZERO_BLOCKS) * 256 + threadIdx.x;   // 0..16383
        int n = idx >> 7, k = idx & 127;
        float w = Wv[(size_t)k * 128 + n];
        __nv_bfloat16 hi = __float2bfloat16(w);
        __nv_bfloat16 lo = __float2bfloat16(w - __bfloat162float(hi));
        uint32_t off = tile_off(n, k);
        *(__nv_bfloat16*)(g_WimgHi + off) = hi;
        *(__nv_bfloat16*)(g_WimgLo + off) = lo;
    }
}

__global__ void mark_flags_kernel(const int* __restrict__ edge_index) {
    int e = blockIdx.x * blockDim.x + threadIdx.x;
    if (e < N_EDGES) {
        int dst = edge_index[N_EDGES + e];
        if ((unsigned)dst < N_NODES) g_flag[dst] = 1;
    }
}

// ---------------------------------------------------------------------------
// Fused: V = x@Wv (bf16-split mma.sync) -> h = x + V*flag -> LayerNorm
// CTA = 128 rows, 256 threads = 8 warps; warp w owns rows 16w..16w+15.
// ---------------------------------------------------------------------------
#define SM_GAMMA  0
#define SM_BETA   512
#define SM_XHI    1024
#define SM_XLO    (SM_XHI + 32768)
#define SM_WHI    (SM_XLO + 32768)
#define SM_WLO    (SM_WHI + 32768)
#define SM_TOTAL  (SM_WLO + 32768)

__global__ __launch_bounds__(THREADS, 1) void fused_v_ln_kernel(
    const float* __restrict__ x,
    const float* __restrict__ gamma,
    const float* __restrict__ beta,
    float* __restrict__ out)
{
    extern __shared__ char smem[];
    const int tid = threadIdx.x;
    const int row0 = blockIdx.x * M_TILE;

    if (tid < 128) {
        ((float*)(smem + SM_GAMMA))[tid] = gamma[tid];
        ((float*)(smem + SM_BETA))[tid]  = beta[tid];
    }

    // Copy pre-swizzled W hi/lo images (L2-resident after first wave)
#pragma unroll
    for (int i = 0; i < 8; i++) {
        ((uint4*)(smem + SM_WHI))[tid + i * 256] = ((const uint4*)g_WimgHi)[tid + i * 256];
        ((uint4*)(smem + SM_WLO))[tid + i * 256] = ((const uint4*)g_WimgLo)[tid + i * 256];
    }

    // Load x tile (coalesced float4), split to bf16 hi/lo, store swizzled
#pragma unroll
    for (int i = 0; i < 16; i++) {
        int idx4 = tid + i * 256;            // 0..4095
        int r  = idx4 >> 5;
        int c4 = idx4 & 31;
        int rr = min(row0 + r, N_NODES - 1);
        float4 v = ((const float4*)x)[(size_t)rr * 32 + c4];

        __nv_bfloat162 h01, h23, l01, l23;
        h01.x = __float2bfloat16(v.x); h01.y = __float2bfloat16(v.y);
        h23.x = __float2bfloat16(v.z); h23.y = __float2bfloat16(v.w);
        l01.x = __float2bfloat16(v.x - __bfloat162float(h01.x));
        l01.y = __float2bfloat16(v.y - __bfloat162float(h01.y));
        l23.x = __float2bfloat16(v.z - __bfloat162float(h23.x));
        l23.y = __float2bfloat16(v.w - __bfloat162float(h23.y));

        uint32_t off = tile_off(r, c4 << 2);   // 8B-aligned
        *(uint2*)(smem + SM_XHI + off) = make_uint2(*(uint32_t*)&h01, *(uint32_t*)&h23);
        *(uint2*)(smem + SM_XLO + off) = make_uint2(*(uint32_t*)&l01, *(uint32_t*)&l23);
    }
    __syncthreads();

    // ---- mainloop: D = xhi*Whi + xhi*Wlo + xlo*Whi ------------------------
    const int w    = tid >> 5;
    const int lane = tid & 31;
    const int g    = lane >> 2;      // fragment "group" = row-within-8
    const int t    = lane & 3;       // fragment "thread in group"
    const uint32_t xv    = (uint32_t)g << 4;              // swizzle XOR value
    const uint32_t baseA = (uint32_t)(2 * w) * 1024u + (uint32_t)g * 128u;  // row 16w+g
    const uint32_t baseB = (uint32_t)g * 128u;                              // row-in-atom g

    const char* pXHI = smem + SM_XHI;
    const char* pXLO = smem + SM_XLO;
    const char* pWHI = smem + SM_WHI;
    const char* pWLO = smem + SM_WLO;

    float acc[16][4];
#pragma unroll
    for (int nt = 0; nt < 16; nt++)
#pragma unroll
        for (int i = 0; i < 4; i++) acc[nt][i] = 0.0f;

#pragma unroll
    for (int kt = 0; kt < 8; kt++) {
        const uint32_t atom = (kt >= 4) ? 16384u : 0u;
        const uint32_t klo  = (uint32_t)(((16 * kt) & 63) * 2 + 4 * t);
        const uint32_t oLo  = atom + (klo ^ xv);          // k0 + 2t
        const uint32_t oHi  = atom + ((klo + 16u) ^ xv);  // k0 + 8 + 2t

        uint32_t ah[4], al[4];
        ah[0] = *(const uint32_t*)(pXHI + baseA + oLo);
        ah[1] = *(const uint32_t*)(pXHI + baseA + oLo + 1024);
        ah[2] = *(const uint32_t*)(pXHI + baseA + oHi);
        ah[3] = *(const uint32_t*)(pXHI + baseA + oHi + 1024);
        al[0] = *(const uint32_t*)(pXLO + baseA + oLo);
        al[1] = *(const uint32_t*)(pXLO + baseA + oLo + 1024);
        al[2] = *(const uint32_t*)(pXLO + baseA + oHi);
        al[3] = *(const uint32_t*)(pXLO + baseA + oHi + 1024);

#pragma unroll
        for (int nt = 0; nt < 16; nt++) {
            const uint32_t bo  = (uint32_t)nt * 1024u + baseB + oLo;
            const uint32_t bo2 = (uint32_t)nt * 1024u + baseB + oHi;
            uint32_t bh[2], bl[2];
            bh[0] = *(const uint32_t*)(pWHI + bo);
            bh[1] = *(const uint32_t*)(pWHI + bo2);
            bl[0] = *(const uint32_t*)(pWLO + bo);
            bl[1] = *(const uint32_t*)(pWLO + bo2);
            mma16816(acc[nt], ah, bh);
            mma16816(acc[nt], ah, bl);
            mma16816(acc[nt], al, bh);
        }
    }

    // ---- epilogue: h = x + V*flag, LayerNorm, store -----------------------
    // Fragment layout: thread holds rows r0=16w+g, r1=r0+8; cols 8nt+2t, +1.
    const int r0 = 16 * w + g;
    const int r1 = r0 + 8;
    const int row0g = row0 + r0;
    const int row1g = row0 + r1;
    const int rc0 = min(row0g, N_NODES - 1);
    const int rc1 = min(row1g, N_NODES - 1);

    const float fac0 = (float)g_flag[rc0];
    const float fac1 = (float)g_flag[rc1];

    float s0 = 0.0f, s1 = 0.0f;
#pragma unroll
    for (int nt = 0; nt < 16; nt++) {
        const int c = 8 * nt + 2 * t;
        float2 x0 = *(const float2*)(x + (size_t)rc0 * 128 + c);
        float2 x1 = *(const float2*)(x + (size_t)rc1 * 128 + c);
        float h00 = fmaf(acc[nt][0], fac0, x0.x);
        float h01 = fmaf(acc[nt][1], fac0, x0.y);
        float h10 = fmaf(acc[nt][2], fac1, x1.x);
        float h11 = fmaf(acc[nt][3], fac1, x1.y);
        acc[nt][0] = h00; acc[nt][1] = h01;
        acc[nt][2] = h10; acc[nt][3] = h11;
        s0 += h00 + h01;
        s1 += h10 + h11;
    }
    // quad reduce (lanes 4g..4g+3 share a row)
    s0 += __shfl_xor_sync(0xffffffffu, s0, 1);
    s0 += __shfl_xor_sync(0xffffffffu, s0, 2);
    s1 += __shfl_xor_sync(0xffffffffu, s1, 1);
    s1 += __shfl_xor_sync(0xffffffffu, s1, 2);
    const float mu0 = s0 * (1.0f / 128.0f);
    const float mu1 = s1 * (1.0f / 128.0f);

    float q0 = 0.0f, q1 = 0.0f;
#pragma unroll
    for (int nt = 0; nt < 16; nt++) {
        float d00 = acc[nt][0] - mu0, d01 = acc[nt][1] - mu0;
        float d10 = acc[nt][2] - mu1, d11 = acc[nt][3] - mu1;
        q0 = fmaf(d00, d00, fmaf(d01, d01, q0));
        q1 = fmaf(d10, d10, fmaf(d11, d11, q1));
    }
    q0 += __shfl_xor_sync(0xffffffffu, q0, 1);
    q0 += __shfl_xor_sync(0xffffffffu, q0, 2);
    q1 += __shfl_xor_sync(0xffffffffu, q1, 1);
    q1 += __shfl_xor_sync(0xffffffffu, q1, 2);
    const float inv0 = rsqrtf(q0 * (1.0f / 128.0f) + 1e-5f);
    const float inv1 = rsqrtf(q1 * (1.0f / 128.0f) + 1e-5f);

    const float* sg = (const float*)(smem + SM_GAMMA);
    const float* sb = (const float*)(smem + SM_BETA);
#pragma unroll
    for (int nt = 0; nt < 16; nt++) {
        const int c = 8 * nt + 2 * t;
        float2 gm = *(const float2*)(sg + c);
        float2 bt = *(const float2*)(sb + c);
        if (row0g < N_NODES) {
            float2 o;
            o.x = fmaf((acc[nt][0] - mu0) * inv0, gm.x, bt.x);
            o.y = fmaf((acc[nt][1] - mu0) * inv0, gm.y, bt.y);
            *(float2*)(out + (size_t)row0g * 128 + c) = o;
        }
        if (row1g < N_NODES) {
            float2 o;
            o.x = fmaf((acc[nt][2] - mu1) * inv1, gm.x, bt.x);
            o.y = fmaf((acc[nt][3] - mu1) * inv1, gm.y, bt.y);
            *(float2*)(out + (size_t)row1g * 128 + c) = o;
        }
    }
}

// ---------------------------------------------------------------------------
extern "C" void kernel_launch(void* const* d_in, const int* in_sizes, int n_in,
                              void* d_out, int out_size)
{
    const float* x          = (const float*)d_in[0];
    const int*   edge_index = (const int*)d_in[1];
    const float* Wv         = (const float*)d_in[5];
    const float* gamma      = (const float*)d_in[7];
    const float* beta       = (const float*)d_in[8];
    float*       out        = (float*)d_out;

    cudaFuncSetAttribute(fused_v_ln_kernel,
                         cudaFuncAttributeMaxDynamicSharedMemorySize, SM_TOTAL);

    prep_kernel<<<ZERO_BLOCKS + 64, 256>>>(Wv);
    mark_flags_kernel<<<(N_EDGES + 255) / 256, 256>>>(edge_index);
    fused_v_ln_kernel<<<N_BLOCKS, THREADS, SM_TOTAL>>>(x, gamma, beta, out);
}

// round 7
// speedup vs baseline: 8.4294x; 1.0388x over previous
#include <cuda_runtime.h>
#include <cuda_bf16.h>
#include <cstdint>

#define N_NODES 50000
#define N_EDGES 800000

#define M_TILE   128
#define THREADS  512
#define N_BLOCKS ((N_NODES + M_TILE - 1) / M_TILE)   // 391

// ---------------------------------------------------------------------------
// Device scratch. g_flag invariant: zero before every kernel_launch invocation
// (zero at module load; fused kernel re-zeroes its rows after use each run).
// ---------------------------------------------------------------------------
__device__ int g_flag[N_NODES];
__device__ __align__(16) unsigned char g_WimgHi[32768];   // swizzled bf16 Wv^T hi
__device__ __align__(16) unsigned char g_WimgLo[32768];   // swizzled bf16 Wv^T lo

// ---------------------------------------------------------------------------
// Blocked SW128 atom layout for a [128 x 128] bf16 tile.
// atom = 8 rows x 64 bf16 (1024B); atom index = (r>>3) + (k>>6)*16.
// Swizzle XOR reduces to ((r&7)<<4) on the low chunk bits.
// ---------------------------------------------------------------------------
__host__ __device__ __forceinline__ uint32_t tile_off(int r, int k) {
    uint32_t off = ((uint32_t)((r >> 3) + ((k >> 6) << 4))) * 1024u
                 + (uint32_t)(r & 7) * 128u + (uint32_t)(k & 63) * 2u;
    return off ^ ((off >> 3) & 0x70);
}

// ---------------------------------------------------------------------------
__device__ __forceinline__ uint32_t smem_u32(const void* p) {
    uint32_t a;
    asm("{ .reg .u64 t; cvta.to.shared.u64 t, %1; cvt.u32.u64 %0, t; }" : "=r"(a) : "l"(p));
    return a;
}

__device__ __forceinline__ void mma16816(float* d, const uint32_t* a, const uint32_t* b) {
    asm volatile(
        "mma.sync.aligned.m16n8k16.row.col.f32.bf16.bf16.f32 "
        "{%0,%1,%2,%3}, {%4,%5,%6,%7}, {%8,%9}, {%0,%1,%2,%3};"
        : "+f"(d[0]), "+f"(d[1]), "+f"(d[2]), "+f"(d[3])
        : "r"(a[0]), "r"(a[1]), "r"(a[2]), "r"(a[3]), "r"(b[0]), "r"(b[1]));
}

__device__ __forceinline__ void ldmx4(uint32_t* r, uint32_t addr) {
    asm volatile("ldmatrix.sync.aligned.m8n8.x4.shared.b16 {%0,%1,%2,%3}, [%4];"
                 : "=r"(r[0]), "=r"(r[1]), "=r"(r[2]), "=r"(r[3]) : "r"(addr));
}

// ---------------------------------------------------------------------------
// Kernel 1: W-convert (blocks 0..63) + edge-dst marking (blocks 64..)
// No ordering needed between the two halves; flags are pre-zeroed.
// ---------------------------------------------------------------------------
#define W_BLOCKS    64
#define MARK_CHUNK  (N_EDGES / 4)                       // 200000 int4 loads
#define MARK_BLOCKS ((MARK_CHUNK + 255) / 256)          // 782

__global__ void prep_mark_kernel(const float* __restrict__ Wv,
                                 const int* __restrict__ edge_index) {
    int b = blockIdx.x;
    if (b < W_BLOCKS) {
        int idx = b * 256 + threadIdx.x;                // 0..16383
        int n = idx >> 7, k = idx & 127;
        float w = Wv[(size_t)k * 128 + n];
        __nv_bfloat16 hi = __float2bfloat16(w);
        __nv_bfloat16 lo = __float2bfloat16(w - __bfloat162float(hi));
        uint32_t off = tile_off(n, k);
        *(__nv_bfloat16*)(g_WimgHi + off) = hi;
        *(__nv_bfloat16*)(g_WimgLo + off) = lo;
    } else {
        int idx = (b - W_BLOCKS) * 256 + threadIdx.x;
        if (idx < MARK_CHUNK) {
            int4 d = ((const int4*)(edge_index + N_EDGES))[idx];
            if ((unsigned)d.x < N_NODES) g_flag[d.x] = 1;
            if ((unsigned)d.y < N_NODES) g_flag[d.y] = 1;
            if ((unsigned)d.z < N_NODES) g_flag[d.z] = 1;
            if ((unsigned)d.w < N_NODES) g_flag[d.w] = 1;
        }
    }
}

// ---------------------------------------------------------------------------
// Fused: V = x@Wv (bf16-split mma.sync) -> h = x + V*flag -> LayerNorm.
// CTA = 128 rows, 512 threads = 16 warps. Warp w: rows 16*(w>>1)..+15,
// column half 64*(w&1)..+63 (8 n-tiles). Zeroes its flags at the end.
// ---------------------------------------------------------------------------
#define SM_GAMMA  0
#define SM_BETA   512
#define SM_PSUM   1024                 // float[128][2]
#define SM_PSQ    2048                 // float[128][2]
#define SM_XHI    3072
#define SM_XLO    (SM_XHI + 32768)
#define SM_WHI    (SM_XLO + 32768)
#define SM_WLO    (SM_WHI + 32768)
#define SM_TOTAL  (SM_WLO + 32768)

__global__ __launch_bounds__(THREADS, 1) void fused_v_ln_kernel(
    const float* __restrict__ x,
    const float* __restrict__ gamma,
    const float* __restrict__ beta,
    float* __restrict__ out)
{
    extern __shared__ char smem[];
    const uint32_t sbase = smem_u32(smem);
    const int tid  = threadIdx.x;
    const int w    = tid >> 5;
    const int lane = tid & 31;
    const int rw   = w >> 1;           // row group 0..7
    const int ch   = w & 1;            // column half
    const int row0 = blockIdx.x * M_TILE;

    if (tid < 128) {
        ((float*)(smem + SM_GAMMA))[tid] = gamma[tid];
        ((float*)(smem + SM_BETA))[tid]  = beta[tid];
    }

    // Copy pre-swizzled W hi/lo (L2-resident after first wave)
#pragma unroll
    for (int i = 0; i < 4; i++) {
        ((uint4*)(smem + SM_WHI))[tid + i * 512] = ((const uint4*)g_WimgHi)[tid + i * 512];
        ((uint4*)(smem + SM_WLO))[tid + i * 512] = ((const uint4*)g_WimgLo)[tid + i * 512];
    }

    // Load x tile (coalesced float4), split to bf16 hi/lo, store swizzled
#pragma unroll
    for (int i = 0; i < 8; i++) {
        int idx4 = tid + i * 512;            // 0..4095
        int r  = idx4 >> 5;
        int c4 = idx4 & 31;
        int rr = min(row0 + r, N_NODES - 1);
        float4 v = ((const float4*)x)[(size_t)rr * 32 + c4];

        __nv_bfloat162 h01, h23, l01, l23;
        h01.x = __float2bfloat16(v.x); h01.y = __float2bfloat16(v.y);
        h23.x = __float2bfloat16(v.z); h23.y = __float2bfloat16(v.w);
        l01.x = __float2bfloat16(v.x - __bfloat162float(h01.x));
        l01.y = __float2bfloat16(v.y - __bfloat162float(h01.y));
        l23.x = __float2bfloat16(v.z - __bfloat162float(h23.x));
        l23.y = __float2bfloat16(v.w - __bfloat162float(h23.y));

        uint32_t off = tile_off(r, c4 << 2);
        *(uint2*)(smem + SM_XHI + off) = make_uint2(*(uint32_t*)&h01, *(uint32_t*)&h23);
        *(uint2*)(smem + SM_XLO + off) = make_uint2(*(uint32_t*)&l01, *(uint32_t*)&l23);
    }
    __syncthreads();

    // ---- ldmatrix lane address precompute ---------------------------------
    // A.x4: matrices {rows g..g+7 kLo, rows+8 kLo, rows kHi, rows+8 kHi}
    const int selA = lane >> 3;
    const int rA   = 16 * rw + (lane & 7) + ((selA & 1) << 3);
    const int kOffA = (selA & 2) << 2;                       // 0 or 8
    const uint32_t rbaseA = (uint32_t)(rA >> 3) * 1024u + (uint32_t)(rA & 7) * 128u;
    const uint32_t xorA   = (uint32_t)(rA & 7) << 4;

    // B.x4: matrices {b0(nt), b1(nt), b0(nt+1), b1(nt+1)}
    const int selB = lane >> 3;
    const int ntSel = selB >> 1;                              // 0 -> nt, 1 -> nt+1
    const int kOffB = (selB & 1) << 3;                        // 0 or 8
    const int nB_lane = (lane & 7);

    float acc[8][4];
#pragma unroll
    for (int nt = 0; nt < 8; nt++)
#pragma unroll
        for (int i = 0; i < 4; i++) acc[nt][i] = 0.0f;

#pragma unroll
    for (int kt = 0; kt < 8; kt++) {
        const uint32_t katomA = (uint32_t)(((16 * kt + kOffA) >> 6) << 14);
        const uint32_t klowA  = (uint32_t)(((16 * kt + kOffA) & 63) * 2);
        const uint32_t offA   = rbaseA + katomA + (klowA ^ xorA);

        uint32_t ah[4], al[4];
        ldmx4(ah, sbase + SM_XHI + offA);
        ldmx4(al, sbase + SM_XLO + offA);

        const uint32_t katomB = (uint32_t)(((16 * kt + kOffB) >> 6) << 14);
        const uint32_t klowB  = (uint32_t)(((16 * kt + kOffB) & 63) * 2);

#pragma unroll
        for (int ntp = 0; ntp < 4; ntp++) {
            const int nt0 = 8 * ch + 2 * ntp;
            const int nB  = 8 * (nt0 + ntSel) + nB_lane;
            const uint32_t offB = (uint32_t)(nB >> 3) * 1024u + (uint32_t)(nB & 7) * 128u
                                + katomB + (klowB ^ ((uint32_t)(nB & 7) << 4));
            uint32_t bh[4], bl[4];
            ldmx4(bh, sbase + SM_WHI + offB);
            ldmx4(bl, sbase + SM_WLO + offB);

            mma16816(acc[2 * ntp],     ah, bh);
            mma16816(acc[2 * ntp],     ah, bl);
            mma16816(acc[2 * ntp],     al, bh);
            mma16816(acc[2 * ntp + 1], ah, bh + 2);
            mma16816(acc[2 * ntp + 1], ah, bl + 2);
            mma16816(acc[2 * ntp + 1], al, bh + 2);
        }
    }

    // ---- epilogue ---------------------------------------------------------
    // Thread owns rows r0 = 16*rw + lane/4, r1 = r0+8; cols 64*ch + 8*nt + 2*(lane&3).
    const int g  = lane >> 2;
    const int t  = lane & 3;
    const int r0 = 16 * rw + g;
    const int r1 = r0 + 8;
    const int row0g = row0 + r0;
    const int row1g = row0 + r1;
    const int rc0 = min(row0g, N_NODES - 1);
    const int rc1 = min(row1g, N_NODES - 1);

    const float fac0 = (float)g_flag[rc0];
    const float fac1 = (float)g_flag[rc1];

    float s0 = 0.0f, s1 = 0.0f;
#pragma unroll
    for (int nt = 0; nt < 8; nt++) {
        const int c = 64 * ch + 8 * nt + 2 * t;
        float2 x0 = *(const float2*)(x + (size_t)rc0 * 128 + c);
        float2 x1 = *(const float2*)(x + (size_t)rc1 * 128 + c);
        float h00 = fmaf(acc[nt][0], fac0, x0.x);
        float h01 = fmaf(acc[nt][1], fac0, x0.y);
        float h10 = fmaf(acc[nt][2], fac1, x1.x);
        float h11 = fmaf(acc[nt][3], fac1, x1.y);
        acc[nt][0] = h00; acc[nt][1] = h01;
        acc[nt][2] = h10; acc[nt][3] = h11;
        s0 += h00 + h01;
        s1 += h10 + h11;
    }
    s0 += __shfl_xor_sync(0xffffffffu, s0, 1);
    s0 += __shfl_xor_sync(0xffffffffu, s0, 2);
    s1 += __shfl_xor_sync(0xffffffffu, s1, 1);
    s1 += __shfl_xor_sync(0xffffffffu, s1, 2);

    float* psum = (float*)(smem + SM_PSUM);
    if (t == 0) { psum[r0 * 2 + ch] = s0; psum[r1 * 2 + ch] = s1; }
    __syncthreads();

    // re-zero flags for next replay (all facs already read)
    if (tid < 128) {
        int rz = row0 + tid;
        if (rz < N_NODES) g_flag[rz] = 0;
    }

    const float mu0 = (psum[r0 * 2] + psum[r0 * 2 + 1]) * (1.0f / 128.0f);
    const float mu1 = (psum[r1 * 2] + psum[r1 * 2 + 1]) * (1.0f / 128.0f);

    float q0 = 0.0f, q1 = 0.0f;
#pragma unroll
    for (int nt = 0; nt < 8; nt++) {
        float d00 = acc[nt][0] - mu0, d01 = acc[nt][1] - mu0;
        float d10 = acc[nt][2] - mu1, d11 = acc[nt][3] - mu1;
        q0 = fmaf(d00, d00, fmaf(d01, d01, q0));
        q1 = fmaf(d10, d10, fmaf(d11, d11, q1));
    }
    q0 += __shfl_xor_sync(0xffffffffu, q0, 1);
    q0 += __shfl_xor_sync(0xffffffffu, q0, 2);
    q1 += __shfl_xor_sync(0xffffffffu, q1, 1);
    q1 += __shfl_xor_sync(0xffffffffu, q1, 2);

    float* psq = (float*)(smem + SM_PSQ);
    if (t == 0) { psq[r0 * 2 + ch] = q0; psq[r1 * 2 + ch] = q1; }
    __syncthreads();

    const float inv0 = rsqrtf((psq[r0 * 2] + psq[r0 * 2 + 1]) * (1.0f / 128.0f) + 1e-5f);
    const float inv1 = rsqrtf((psq[r1 * 2] + psq[r1 * 2 + 1]) * (1.0f / 128.0f) + 1e-5f);

    const float* sg = (const float*)(smem + SM_GAMMA);
    const float* sb = (const float*)(smem + SM_BETA);
#pragma unroll
    for (int nt = 0; nt < 8; nt++) {
        const int c = 64 * ch + 8 * nt + 2 * t;
        float2 gm = *(const float2*)(sg + c);
        float2 bt = *(const float2*)(sb + c);
        if (row0g < N_NODES) {
            float2 o;
            o.x = fmaf((acc[nt][0] - mu0) * inv0, gm.x, bt.x);
            o.y = fmaf((acc[nt][1] - mu0) * inv0, gm.y, bt.y);
            *(float2*)(out + (size_t)row0g * 128 + c) = o;
        }
        if (row1g < N_NODES) {
            float2 o;
            o.x = fmaf((acc[nt][2] - mu1) * inv1, gm.x, bt.x);
            o.y = fmaf((acc[nt][3] - mu1) * inv1, gm.y, bt.y);
            *(float2*)(out + (size_t)row1g * 128 + c) = o;
        }
    }
}

// ---------------------------------------------------------------------------
extern "C" void kernel_launch(void* const* d_in, const int* in_sizes, int n_in,
                              void* d_out, int out_size)
{
    const float* x          = (const float*)d_in[0];
    const int*   edge_index = (const int*)d_in[1];
    const float* Wv         = (const float*)d_in[5];
    const float* gamma      = (const float*)d_in[7];
    const float* beta       = (const float*)d_in[8];
    float*       out        = (float*)d_out;

    cudaFuncSetAttribute(fused_v_ln_kernel,
                         cudaFuncAttributeMaxDynamicSharedMemorySize, SM_TOTAL);

    prep_mark_kernel<<<W_BLOCKS + MARK_BLOCKS, 256>>>(Wv, edge_index);
    fused_v_ln_kernel<<<N_BLOCKS, THREADS, SM_TOTAL>>>(x, gamma, beta, out);
}